// round 6
// baseline (speedup 1.0000x reference)
#include <cuda_runtime.h>
#include <math.h>

// Problem constants
#define B_  32
#define C_  1024
#define M_  1024
#define D_  512
#define R_  64
#define NCC 16   // c-chunks for KV partial sums

// Scratch (device globals: allocation-free per harness rules)
__device__ float g_Tsum[B_ * C_];          // (b,c)  = sum_m T[b,c,m]
__device__ float g_rsum[R_];               // (r)    = sum_m R[r,m]
__device__ float g_partK[NCC * B_ * D_];   // partial Ksum per c-chunk
__device__ float g_partV[NCC * B_ * D_];
__device__ float g_Ksum[B_ * D_];
__device__ float g_Vsum[B_ * D_];
__device__ float g_u[B_ * C_];             // scale * Wq . Ksum
__device__ float g_ypart[4][B_ * C_];      // d-chunk partials of Vsum . Wout[:,c]
__device__ float g_w[B_ * M_];             // softmax-weighted rsum

// ---------------------------------------------------------------------------
// K1: row sums of T (B*C rows) and R_full (R rows). One warp per row, float4,
// 4 independent accumulators.
// ---------------------------------------------------------------------------
__global__ void __launch_bounds__(256)
k_rowsum(const float* __restrict__ T, const float* __restrict__ Rf)
{
    const int gw   = (blockIdx.x * 256 + threadIdx.x) >> 5;
    const int lane = threadIdx.x & 31;
    const float* src;
    float* dst;
    if (gw < B_ * C_)            { src = T  + (long)gw * M_;              dst = g_Tsum + gw; }
    else if (gw < B_ * C_ + R_)  { src = Rf + (long)(gw - B_ * C_) * M_;  dst = g_rsum + (gw - B_ * C_); }
    else return;

    float s0 = 0.f, s1 = 0.f, s2 = 0.f, s3 = 0.f;
    #pragma unroll
    for (int j = 0; j < M_ / 256; ++j) {          // 4 iterations, 2 loads each
        float4 a = *(const float4*)&src[j * 256 + lane * 4];
        float4 b = *(const float4*)&src[j * 256 + 128 + lane * 4];
        s0 += a.x + a.y; s1 += a.z + a.w;
        s2 += b.x + b.y; s3 += b.z + b.w;
    }
    float acc = (s0 + s1) + (s2 + s3);
    #pragma unroll
    for (int off = 16; off; off >>= 1)
        acc += __shfl_xor_sync(0xffffffffu, acc, off);
    if (lane == 0) *dst = acc;
}

// ---------------------------------------------------------------------------
// K2: partial Ksum/Vsum over a 64-wide c-chunk. grid (NCC, B/4), 512 threads.
// ---------------------------------------------------------------------------
__global__ void __launch_bounds__(512)
k_kv_partial(const float* __restrict__ Wk, const float* __restrict__ Wv)
{
    __shared__ float ts[4][64];
    const int d  = threadIdx.x;
    const int c0 = blockIdx.x * 64;
    const int b0 = blockIdx.y * 4;

    if (threadIdx.x < 256) {
        const int j = threadIdx.x >> 6, cc = threadIdx.x & 63;
        ts[j][cc] = g_Tsum[(b0 + j) * C_ + c0 + cc];
    }
    __syncthreads();

    float aK[4] = {}, aV[4] = {};
    #pragma unroll 4
    for (int cc = 0; cc < 64; ++cc) {
        const float wk = Wk[(long)(c0 + cc) * D_ + d];
        const float wv = Wv[(long)(c0 + cc) * D_ + d];
        #pragma unroll
        for (int j = 0; j < 4; ++j) {
            aK[j] = fmaf(ts[j][cc], wk, aK[j]);
            aV[j] = fmaf(ts[j][cc], wv, aV[j]);
        }
    }
    #pragma unroll
    for (int j = 0; j < 4; ++j) {
        g_partK[((long)blockIdx.x * B_ + b0 + j) * D_ + d] = aK[j];
        g_partV[((long)blockIdx.x * B_ + b0 + j) * D_ + d] = aV[j];
    }
}

// K2b: combine partials. grid (B), 512 threads.
__global__ void __launch_bounds__(512)
k_kv_combine()
{
    const int b = blockIdx.x, d = threadIdx.x;
    float sK = 0.f, sV = 0.f;
    #pragma unroll
    for (int p = 0; p < NCC; ++p) {
        sK += g_partK[((long)p * B_ + b) * D_ + d];
        sV += g_partV[((long)p * B_ + b) * D_ + d];
    }
    g_Ksum[b * D_ + d] = sK;
    g_Vsum[b * D_ + d] = sV;
}

// ---------------------------------------------------------------------------
// K3a: u[b,c] = scale * sum_d Wq[c,d]*Ksum[b,d].
// Block = 8 c x 32 b (grid C/8). Ksum staged transposed in smem (pad 33 ->
// conflict-free LDS with lanes over b); Wq read warp-uniform (line reused 32x).
// ---------------------------------------------------------------------------
__global__ void __launch_bounds__(256)
k_u(const float* __restrict__ Wq, float scale)
{
    __shared__ float ks_t[256][33];
    const int t  = threadIdx.x;
    const int b  = t & 31;
    const int cl = t >> 5;
    const int c  = blockIdx.x * 8 + cl;

    float acc0 = 0.f, acc1 = 0.f;
    #pragma unroll
    for (int p = 0; p < 2; ++p) {
        const int d0 = p * 256;
        __syncthreads();
        #pragma unroll 8
        for (int bl = 0; bl < 32; ++bl)
            ks_t[t][bl] = g_Ksum[bl * D_ + d0 + t];   // coalesced read, cf write
        __syncthreads();

        const float* wq = Wq + (long)c * D_ + d0;
        #pragma unroll 8
        for (int dd = 0; dd < 256; dd += 2) {
            acc0 = fmaf(__ldg(&wq[dd]),     ks_t[dd][b],     acc0);
            acc1 = fmaf(__ldg(&wq[dd + 1]), ks_t[dd + 1][b], acc1);
        }
    }
    g_u[b * C_ + c] = (acc0 + acc1) * scale;
}

// ---------------------------------------------------------------------------
// K3b: y partials. y[b,c] = sum_d Vsum[b,d]*Wout[d,c], split into 4 d-chunks.
// grid (C/128, B/8, 4), 128 threads; Wout reads coalesced, Vsum broadcast.
// ---------------------------------------------------------------------------
__global__ void __launch_bounds__(128)
k_ypart(const float* __restrict__ Wout)
{
    __shared__ float vs[8][128];
    const int t  = threadIdx.x;
    const int c  = blockIdx.x * 128 + t;
    const int bg = blockIdx.y * 8;
    const int d0 = blockIdx.z * 128;

    #pragma unroll
    for (int j = 0; j < 8; ++j) vs[j][t] = g_Vsum[(bg + j) * D_ + d0 + t];
    __syncthreads();

    float acc[8] = {};
    #pragma unroll 4
    for (int dd = 0; dd < 128; ++dd) {
        const float wo = Wout[(long)(d0 + dd) * C_ + c];
        #pragma unroll
        for (int j = 0; j < 8; ++j) acc[j] = fmaf(wo, vs[j][dd], acc[j]);
    }
    #pragma unroll
    for (int j = 0; j < 8; ++j)
        g_ypart[blockIdx.z][(bg + j) * C_ + c] = acc[j];
}

// ---------------------------------------------------------------------------
// K4: x[b,i] = sum_c T[b,c,i]*u[b,c], then softmax over r of x*rsum[r]
//     -> w[b,i] = sum_r A*rsum[r].
// grid (M/64, B), 256 threads: lanes cover 64 i via float2; 8 c-groups of 128.
// ---------------------------------------------------------------------------
__global__ void __launch_bounds__(256)
k_scores(const float* __restrict__ T)
{
    __shared__ float u_s[C_];
    __shared__ float rs_s[R_];
    __shared__ float red[8][64];
    const int t    = threadIdx.x;
    const int lane = t & 31;
    const int cg   = t >> 5;
    const int b    = blockIdx.y;
    const int i0   = blockIdx.x * 64;

    #pragma unroll
    for (int j = 0; j < 4; ++j) u_s[t + j * 256] = g_u[b * C_ + t + j * 256];
    if (t < R_) rs_s[t] = g_rsum[t];
    __syncthreads();

    const float* Tp = T + ((long)b * C_ + cg * 128) * M_ + i0 + lane * 2;
    const float* up = u_s + cg * 128;
    float a0 = 0.f, a1 = 0.f, a2 = 0.f, a3 = 0.f;
    #pragma unroll 8
    for (int c = 0; c < 128; c += 2) {
        const float2 v0 = *(const float2*)&Tp[(long)c * M_];
        const float2 v1 = *(const float2*)&Tp[(long)(c + 1) * M_];
        a0 = fmaf(v0.x, up[c],     a0);
        a1 = fmaf(v0.y, up[c],     a1);
        a2 = fmaf(v1.x, up[c + 1], a2);
        a3 = fmaf(v1.y, up[c + 1], a3);
    }
    red[cg][lane * 2]     = a0 + a2;
    red[cg][lane * 2 + 1] = a1 + a3;
    __syncthreads();

    if (t < 64) {
        float x = 0.f;
        #pragma unroll
        for (int g = 0; g < 8; ++g) x += red[g][t];
        float mx = -1e30f;
        #pragma unroll
        for (int r = 0; r < R_; ++r) mx = fmaxf(mx, x * rs_s[r]);
        float num = 0.f, den = 0.f;
        #pragma unroll
        for (int r = 0; r < R_; ++r) {
            const float e = __expf(x * rs_s[r] - mx);
            den += e;
            num = fmaf(rs_s[r], e, num);
        }
        g_w[b * M_ + i0 + t] = num / den;
    }
}

// ---------------------------------------------------------------------------
// K5: out[b,c,i] = w[b,i] * y[b,c] with y = sum of 4 d-chunk partials.
// grid (B*C/4), 256 threads, float4 stores.
// ---------------------------------------------------------------------------
__global__ void __launch_bounds__(256)
k_outer(float* __restrict__ Out)
{
    const int t  = threadIdx.x;
    const int b  = blockIdx.x >> 8;
    const int c0 = (blockIdx.x & 255) * 4;
    const float4 w4 = *(const float4*)&g_w[b * M_ + t * 4];
    #pragma unroll
    for (int j = 0; j < 4; ++j) {
        const int idx = b * C_ + c0 + j;
        const float yv = g_ypart[0][idx] + g_ypart[1][idx]
                       + g_ypart[2][idx] + g_ypart[3][idx];
        float4 o = make_float4(w4.x * yv, w4.y * yv, w4.z * yv, w4.w * yv);
        *(float4*)&Out[((long)b * C_ + c0 + j) * M_ + t * 4] = o;
    }
}

// ---------------------------------------------------------------------------
extern "C" void kernel_launch(void* const* d_in, const int* in_sizes, int n_in,
                              void* d_out, int out_size)
{
    (void)in_sizes; (void)n_in; (void)out_size;
    const float* T     = (const float*)d_in[0];   // (B, C, M)
    const float* Wq    = (const float*)d_in[1];   // (C, D)
    const float* Wk    = (const float*)d_in[2];   // (C, D)
    const float* Wv    = (const float*)d_in[3];   // (C, DV)
    const float* Wout  = (const float*)d_in[4];   // (DV, C)
    const float* Rfull = (const float*)d_in[5];   // (R, M)
    float* Out = (float*)d_out;                   // (B, C, M)

    const float scale = 1.0f / sqrtf((float)D_);

    k_rowsum<<<(B_ * C_ + R_ + 7) / 8, 256>>>(T, Rfull);
    k_kv_partial<<<dim3(NCC, B_ / 4), 512>>>(Wk, Wv);
    k_kv_combine<<<B_, 512>>>();
    k_u<<<C_ / 8, 256>>>(Wq, scale);
    k_ypart<<<dim3(C_ / 128, B_ / 8, 4), 128>>>(Wout);
    k_scores<<<dim3(M_ / 64, B_), 256>>>(T);
    k_outer<<<B_ * 256, 256>>>(Out);
}

// round 8
// speedup vs baseline: 1.2105x; 1.2105x over previous
#include <cuda_runtime.h>
#include <math.h>

// Problem constants
#define B_  32
#define C_  1024
#define M_  1024
#define D_  512
#define R_  64
#define NCC 16   // c-chunks for KV partial sums

// Scratch (device globals: allocation-free per harness rules)
__device__ float g_Tsum[B_ * C_];          // (b,c)  = sum_m T[b,c,m]
__device__ float g_rsum[R_];               // (r)    = sum_m R[r,m]
__device__ float g_partK[NCC * B_ * D_];   // partial Ksum per c-chunk
__device__ float g_partV[NCC * B_ * D_];
__device__ float g_KsumT[D_ * B_];         // (d,b) transposed for k_u
__device__ float g_Vsum[B_ * D_];          // (b,d)
__device__ float g_u[B_ * C_];             // scale * Wq . Ksum
__device__ float g_ypart[4][B_ * C_];      // d-chunk partials of Vsum . Wout[:,c]

// ---------------------------------------------------------------------------
// K1: row sums of T (B*C rows) and R_full (R rows). One warp per row, float4,
// 4 independent accumulators.
// ---------------------------------------------------------------------------
__global__ void __launch_bounds__(256)
k_rowsum(const float* __restrict__ T, const float* __restrict__ Rf)
{
    const int gw   = (blockIdx.x * 256 + threadIdx.x) >> 5;
    const int lane = threadIdx.x & 31;
    const float* src;
    float* dst;
    if (gw < B_ * C_)            { src = T  + (long)gw * M_;              dst = g_Tsum + gw; }
    else if (gw < B_ * C_ + R_)  { src = Rf + (long)(gw - B_ * C_) * M_;  dst = g_rsum + (gw - B_ * C_); }
    else return;

    float s0 = 0.f, s1 = 0.f, s2 = 0.f, s3 = 0.f;
    #pragma unroll
    for (int j = 0; j < M_ / 256; ++j) {          // 4 iterations, 2 loads each
        float4 a = *(const float4*)&src[j * 256 + lane * 4];
        float4 b = *(const float4*)&src[j * 256 + 128 + lane * 4];
        s0 += a.x + a.y; s1 += a.z + a.w;
        s2 += b.x + b.y; s3 += b.z + b.w;
    }
    float acc = (s0 + s1) + (s2 + s3);
    #pragma unroll
    for (int off = 16; off; off >>= 1)
        acc += __shfl_xor_sync(0xffffffffu, acc, off);
    if (lane == 0) *dst = acc;
}

// ---------------------------------------------------------------------------
// K2: partial Ksum/Vsum over a 64-wide c-chunk. grid (NCC, B/4), 512 threads.
// ---------------------------------------------------------------------------
__global__ void __launch_bounds__(512)
k_kv_partial(const float* __restrict__ Wk, const float* __restrict__ Wv)
{
    __shared__ float ts[4][64];
    const int d  = threadIdx.x;
    const int c0 = blockIdx.x * 64;
    const int b0 = blockIdx.y * 4;

    if (threadIdx.x < 256) {
        const int j = threadIdx.x >> 6, cc = threadIdx.x & 63;
        ts[j][cc] = g_Tsum[(b0 + j) * C_ + c0 + cc];
    }
    __syncthreads();

    float aK[4] = {}, aV[4] = {};
    #pragma unroll 4
    for (int cc = 0; cc < 64; ++cc) {
        const float wk = Wk[(long)(c0 + cc) * D_ + d];
        const float wv = Wv[(long)(c0 + cc) * D_ + d];
        #pragma unroll
        for (int j = 0; j < 4; ++j) {
            aK[j] = fmaf(ts[j][cc], wk, aK[j]);
            aV[j] = fmaf(ts[j][cc], wv, aV[j]);
        }
    }
    #pragma unroll
    for (int j = 0; j < 4; ++j) {
        g_partK[((long)blockIdx.x * B_ + b0 + j) * D_ + d] = aK[j];
        g_partV[((long)blockIdx.x * B_ + b0 + j) * D_ + d] = aV[j];
    }
}

// K2b: combine partials. grid (B), 512 threads. Ksum written transposed.
__global__ void __launch_bounds__(512)
k_kv_combine()
{
    const int b = blockIdx.x, d = threadIdx.x;
    float sK = 0.f, sV = 0.f;
    #pragma unroll
    for (int p = 0; p < NCC; ++p) {
        sK += g_partK[((long)p * B_ + b) * D_ + d];
        sV += g_partV[((long)p * B_ + b) * D_ + d];
    }
    g_KsumT[d * B_ + b] = sK;
    g_Vsum[b * D_ + d]  = sV;
}

// ---------------------------------------------------------------------------
// K3a: u[b,c] = scale * sum_d Wq[c,d]*KsumT[d,b].
// One block per c (grid 1024). Wq row in smem; lanes = b read KsumT coalesced
// (64KB working set, L1/L2 resident). 8 d-groups, smem reduction.
// ---------------------------------------------------------------------------
__global__ void __launch_bounds__(256)
k_u(const float* __restrict__ Wq, float scale)
{
    __shared__ float wq_s[D_];
    __shared__ float red[8][33];
    const int t  = threadIdx.x;
    const int c  = blockIdx.x;
    const int b  = t & 31;
    const int dg = t >> 5;

    wq_s[t]       = Wq[(long)c * D_ + t];
    wq_s[t + 256] = Wq[(long)c * D_ + t + 256];
    __syncthreads();

    const float* kt = g_KsumT + dg * 64 * B_ + b;
    const float* wp = wq_s + dg * 64;
    float a0 = 0.f, a1 = 0.f, a2 = 0.f, a3 = 0.f;
    #pragma unroll
    for (int k = 0; k < 64; k += 4) {
        a0 = fmaf(wp[k + 0], kt[(k + 0) * B_], a0);
        a1 = fmaf(wp[k + 1], kt[(k + 1) * B_], a1);
        a2 = fmaf(wp[k + 2], kt[(k + 2) * B_], a2);
        a3 = fmaf(wp[k + 3], kt[(k + 3) * B_], a3);
    }
    red[dg][b] = (a0 + a1) + (a2 + a3);
    __syncthreads();

    if (t < 32) {
        float u = 0.f;
        #pragma unroll
        for (int g = 0; g < 8; ++g) u += red[g][t];
        g_u[t * C_ + c] = u * scale;
    }
}

// ---------------------------------------------------------------------------
// K3b: y partials. y[b,c] = sum_d Vsum[b,d]*Wout[d,c], split into 4 d-chunks.
// grid (C/128, B/8, 4), 128 threads; Wout reads coalesced, Vsum broadcast.
// ---------------------------------------------------------------------------
__global__ void __launch_bounds__(128)
k_ypart(const float* __restrict__ Wout)
{
    __shared__ float vs[8][128];
    const int t  = threadIdx.x;
    const int c  = blockIdx.x * 128 + t;
    const int bg = blockIdx.y * 8;
    const int d0 = blockIdx.z * 128;

    #pragma unroll
    for (int j = 0; j < 8; ++j) vs[j][t] = g_Vsum[(bg + j) * D_ + d0 + t];
    __syncthreads();

    float acc[8] = {};
    #pragma unroll 4
    for (int dd = 0; dd < 128; ++dd) {
        const float wo = Wout[(long)(d0 + dd) * C_ + c];
        #pragma unroll
        for (int j = 0; j < 8; ++j) acc[j] = fmaf(wo, vs[j][dd], acc[j]);
    }
    #pragma unroll
    for (int j = 0; j < 8; ++j)
        g_ypart[blockIdx.z][(bg + j) * C_ + c] = acc[j];
}

// ---------------------------------------------------------------------------
// K4 (fused): x[b,i] = sum_c T[b,c,i]*u[b,c]; softmax over r of x*rsum[r]
//   -> w[i]; then Out[b,c,i] = w[i]*y[c] written directly.
// grid (M/128, B), 256 threads. i-tile 128 (float4 loads/stores).
// ---------------------------------------------------------------------------
__global__ void __launch_bounds__(256)
k_scores_out(const float* __restrict__ T, float* __restrict__ Out)
{
    __shared__ float u_s[C_];
    __shared__ float y_s[C_];
    __shared__ float rs_s[R_];
    __shared__ float red[8][128];
    __shared__ float w_s[128];
    const int t    = threadIdx.x;
    const int lane = t & 31;
    const int cg   = t >> 5;
    const int b    = blockIdx.y;
    const int i0   = blockIdx.x * 128;

    #pragma unroll
    for (int j = 0; j < 4; ++j) {
        const int idx = b * C_ + t + j * 256;
        u_s[t + j * 256] = g_u[idx];
        y_s[t + j * 256] = g_ypart[0][idx] + g_ypart[1][idx]
                         + g_ypart[2][idx] + g_ypart[3][idx];
    }
    if (t < R_) rs_s[t] = g_rsum[t];
    __syncthreads();

    // ---- x accumulation: 8 c-groups of 128, float4 over i ----
    const float* Tp = T + ((long)b * C_ + cg * 128) * M_ + i0 + lane * 4;
    const float* up = u_s + cg * 128;
    float4 acc = make_float4(0.f, 0.f, 0.f, 0.f);
    #pragma unroll 4
    for (int c = 0; c < 128; ++c) {
        const float4 v = *(const float4*)&Tp[(long)c * M_];
        const float uu = up[c];
        acc.x = fmaf(v.x, uu, acc.x);
        acc.y = fmaf(v.y, uu, acc.y);
        acc.z = fmaf(v.z, uu, acc.z);
        acc.w = fmaf(v.w, uu, acc.w);
    }
    *(float4*)&red[cg][lane * 4] = acc;
    __syncthreads();

    // ---- reduce + softmax-weighted rsum ----
    if (t < 128) {
        float x = 0.f;
        #pragma unroll
        for (int g = 0; g < 8; ++g) x += red[g][t];
        float mx = -1e30f;
        #pragma unroll
        for (int r = 0; r < R_; ++r) mx = fmaxf(mx, x * rs_s[r]);
        float num = 0.f, den = 0.f;
        #pragma unroll
        for (int r = 0; r < R_; ++r) {
            const float e = __expf(x * rs_s[r] - mx);
            den += e;
            num = fmaf(rs_s[r], e, num);
        }
        w_s[t] = num / den;
    }
    __syncthreads();

    // ---- write Out[b, c, i-tile]: warp per c, 512B coalesced stores ----
    const int i4 = lane * 4;
    const float4 w4 = *(const float4*)&w_s[i4];
    float* op = Out + (long)b * C_ * M_ + i0 + i4;
    #pragma unroll 4
    for (int c = cg; c < C_; c += 8) {
        const float yv = y_s[c];
        float4 o = make_float4(w4.x * yv, w4.y * yv, w4.z * yv, w4.w * yv);
        *(float4*)&op[(long)c * M_] = o;
    }
}

// ---------------------------------------------------------------------------
extern "C" void kernel_launch(void* const* d_in, const int* in_sizes, int n_in,
                              void* d_out, int out_size)
{
    (void)in_sizes; (void)n_in; (void)out_size;
    const float* T     = (const float*)d_in[0];   // (B, C, M)
    const float* Wq    = (const float*)d_in[1];   // (C, D)
    const float* Wk    = (const float*)d_in[2];   // (C, D)
    const float* Wv    = (const float*)d_in[3];   // (C, DV)
    const float* Wout  = (const float*)d_in[4];   // (DV, C)
    const float* Rfull = (const float*)d_in[5];   // (R, M)
    float* Out = (float*)d_out;                   // (B, C, M)

    const float scale = 1.0f / sqrtf((float)D_);

    k_rowsum<<<(B_ * C_ + R_ + 7) / 8, 256>>>(T, Rfull);
    k_kv_partial<<<dim3(NCC, B_ / 4), 512>>>(Wk, Wv);
    k_kv_combine<<<B_, 512>>>();
    k_u<<<C_, 256>>>(Wq, scale);
    k_ypart<<<dim3(C_ / 128, B_ / 8, 4), 128>>>(Wout);
    k_scores_out<<<dim3(M_ / 128, B_), 256>>>(T, Out);
}

// round 9
// speedup vs baseline: 1.4139x; 1.1680x over previous
#include <cuda_runtime.h>
#include <math.h>

// Problem constants
#define B_  32
#define C_  1024
#define M_  1024
#define D_  512
#define R_  64
#define NCC 16   // c-chunks for KV partial sums

// Scratch (device globals: allocation-free per harness rules)
__device__ float g_Tsum[B_ * C_];          // (b,c)  = sum_m T[b,c,m]
__device__ float g_rsum[R_];               // (r)    = sum_m R[r,m]
__device__ float g_partK[NCC * B_ * D_];   // partial Ksum per c-chunk
__device__ float g_partV[NCC * B_ * D_];
__device__ float g_KsumT[D_ * B_];         // (d,b) transposed for u
__device__ float g_Vsum[B_ * D_];          // (b,d)
__device__ float g_u[B_ * C_];             // scale * Wq . Ksum
__device__ float g_ypart[4][B_ * C_];      // d-chunk partials of Vsum . Wout[:,c]

// ---------------------------------------------------------------------------
// K1: row sums of T (B*C rows) and R_full (R rows). One warp per row, float4,
// 4 independent accumulators.
// ---------------------------------------------------------------------------
__global__ void __launch_bounds__(256)
k_rowsum(const float* __restrict__ T, const float* __restrict__ Rf)
{
    const int gw   = (blockIdx.x * 256 + threadIdx.x) >> 5;
    const int lane = threadIdx.x & 31;
    const float* src;
    float* dst;
    if (gw < B_ * C_)            { src = T  + (long)gw * M_;              dst = g_Tsum + gw; }
    else if (gw < B_ * C_ + R_)  { src = Rf + (long)(gw - B_ * C_) * M_;  dst = g_rsum + (gw - B_ * C_); }
    else return;

    float s0 = 0.f, s1 = 0.f, s2 = 0.f, s3 = 0.f;
    #pragma unroll
    for (int j = 0; j < M_ / 256; ++j) {          // 4 iterations, 2 loads each
        float4 a = *(const float4*)&src[j * 256 + lane * 4];
        float4 b = *(const float4*)&src[j * 256 + 128 + lane * 4];
        s0 += a.x + a.y; s1 += a.z + a.w;
        s2 += b.x + b.y; s3 += b.z + b.w;
    }
    float acc = (s0 + s1) + (s2 + s3);
    #pragma unroll
    for (int off = 16; off; off >>= 1)
        acc += __shfl_xor_sync(0xffffffffu, acc, off);
    if (lane == 0) *dst = acc;
}

// ---------------------------------------------------------------------------
// K2: partial Ksum/Vsum over a 64-wide c-chunk. grid (NCC, B/4), 512 threads.
// ---------------------------------------------------------------------------
__global__ void __launch_bounds__(512)
k_kv_partial(const float* __restrict__ Wk, const float* __restrict__ Wv)
{
    __shared__ float ts[4][64];
    const int d  = threadIdx.x;
    const int c0 = blockIdx.x * 64;
    const int b0 = blockIdx.y * 4;

    if (threadIdx.x < 256) {
        const int j = threadIdx.x >> 6, cc = threadIdx.x & 63;
        ts[j][cc] = g_Tsum[(b0 + j) * C_ + c0 + cc];
    }
    __syncthreads();

    float aK[4] = {}, aV[4] = {};
    #pragma unroll 4
    for (int cc = 0; cc < 64; ++cc) {
        const float wk = Wk[(long)(c0 + cc) * D_ + d];
        const float wv = Wv[(long)(c0 + cc) * D_ + d];
        #pragma unroll
        for (int j = 0; j < 4; ++j) {
            aK[j] = fmaf(ts[j][cc], wk, aK[j]);
            aV[j] = fmaf(ts[j][cc], wv, aV[j]);
        }
    }
    #pragma unroll
    for (int j = 0; j < 4; ++j) {
        g_partK[((long)blockIdx.x * B_ + b0 + j) * D_ + d] = aK[j];
        g_partV[((long)blockIdx.x * B_ + b0 + j) * D_ + d] = aV[j];
    }
}

// K2b: combine partials. grid (B), 512 threads. Ksum written transposed.
__global__ void __launch_bounds__(512)
k_kv_combine()
{
    const int b = blockIdx.x, d = threadIdx.x;
    float sK = 0.f, sV = 0.f;
    #pragma unroll
    for (int p = 0; p < NCC; ++p) {
        sK += g_partK[((long)p * B_ + b) * D_ + d];
        sV += g_partV[((long)p * B_ + b) * D_ + d];
    }
    g_KsumT[d * B_ + b] = sK;
    g_Vsum[b * D_ + d]  = sV;
}

// ---------------------------------------------------------------------------
// K3 (merged): blocks [0, C_)            -> u[b,c] for one c
//              blocks [C_, C_ + 64)      -> ypart chunk
// 256 threads everywhere.
// ---------------------------------------------------------------------------
__global__ void __launch_bounds__(256)
k_uy(const float* __restrict__ Wq, const float* __restrict__ Wout, float scale)
{
    const int t = threadIdx.x;

    if (blockIdx.x < C_) {
        // ---- u[b,c] = scale * sum_d Wq[c,d]*KsumT[d,b] ----
        __shared__ float wq_s[D_];
        __shared__ float red[8][33];
        const int c  = blockIdx.x;
        const int b  = t & 31;
        const int dg = t >> 5;

        wq_s[t]       = Wq[(long)c * D_ + t];
        wq_s[t + 256] = Wq[(long)c * D_ + t + 256];
        __syncthreads();

        const float* kt = g_KsumT + dg * 64 * B_ + b;
        const float* wp = wq_s + dg * 64;
        float a0 = 0.f, a1 = 0.f, a2 = 0.f, a3 = 0.f;
        #pragma unroll
        for (int k = 0; k < 64; k += 4) {
            a0 = fmaf(wp[k + 0], kt[(k + 0) * B_], a0);
            a1 = fmaf(wp[k + 1], kt[(k + 1) * B_], a1);
            a2 = fmaf(wp[k + 2], kt[(k + 2) * B_], a2);
            a3 = fmaf(wp[k + 3], kt[(k + 3) * B_], a3);
        }
        red[dg][b] = (a0 + a1) + (a2 + a3);
        __syncthreads();

        if (t < 32) {
            float u = 0.f;
            #pragma unroll
            for (int g = 0; g < 8; ++g) u += red[g][t];
            g_u[t * C_ + c] = u * scale;
        }
    } else {
        // ---- ypart[z][bg+j, c] = sum_{dd in chunk z} Vsum*Wout ----
        __shared__ float vs[8][128];
        const int idx = blockIdx.x - C_;      // 0..63
        const int z   = idx & 3;
        const int bg  = ((idx >> 2) & 3) * 8;
        const int c   = (idx >> 4) * 256 + t;
        const int d0  = z * 128;

        {
            const int j = t >> 5, dd = (t & 31) * 4;
            const float4 v = *(const float4*)&g_Vsum[(bg + j) * D_ + d0 + dd];
            *(float4*)&vs[j][dd] = v;
        }
        __syncthreads();

        float acc[8] = {};
        #pragma unroll 4
        for (int dd = 0; dd < 128; ++dd) {
            const float wo = Wout[(long)(d0 + dd) * C_ + c];
            #pragma unroll
            for (int j = 0; j < 8; ++j) acc[j] = fmaf(wo, vs[j][dd], acc[j]);
        }
        #pragma unroll
        for (int j = 0; j < 8; ++j)
            g_ypart[z][(bg + j) * C_ + c] = acc[j];
    }
}

// ---------------------------------------------------------------------------
// K4 (fused): x[b,i] = sum_c T[b,c,i]*u[b,c]; softmax over r of x*rsum[r]
//   -> w[i]; then Out[b,c,i] = w[i]*y[c] written directly.
// grid (M/128, B), 512 threads (16 warps -> ~28 warps/SM at 256 blocks).
// ---------------------------------------------------------------------------
__global__ void __launch_bounds__(512)
k_scores_out(const float* __restrict__ T, float* __restrict__ Out)
{
    __shared__ float u_s[C_];
    __shared__ float y_s[C_];
    __shared__ float rs_s[R_];
    __shared__ float red[16][128];
    __shared__ float w_s[128];
    const int t    = threadIdx.x;
    const int lane = t & 31;
    const int cg   = t >> 5;                 // 0..15
    const int b    = blockIdx.y;
    const int i0   = blockIdx.x * 128;

    #pragma unroll
    for (int j = 0; j < 2; ++j) {
        const int idx = b * C_ + t + j * 512;
        u_s[t + j * 512] = g_u[idx];
        y_s[t + j * 512] = g_ypart[0][idx] + g_ypart[1][idx]
                         + g_ypart[2][idx] + g_ypart[3][idx];
    }
    if (t < R_) rs_s[t] = g_rsum[t];
    __syncthreads();

    // ---- x accumulation: 16 c-groups of 64, float4 over i, unroll 8 ----
    const float* Tp = T + ((long)b * C_ + cg * 64) * M_ + i0 + lane * 4;
    const float* up = u_s + cg * 64;
    float4 acc = make_float4(0.f, 0.f, 0.f, 0.f);
    #pragma unroll 8
    for (int c = 0; c < 64; ++c) {
        const float4 v = *(const float4*)&Tp[(long)c * M_];
        const float uu = up[c];
        acc.x = fmaf(v.x, uu, acc.x);
        acc.y = fmaf(v.y, uu, acc.y);
        acc.z = fmaf(v.z, uu, acc.z);
        acc.w = fmaf(v.w, uu, acc.w);
    }
    *(float4*)&red[cg][lane * 4] = acc;
    __syncthreads();

    // ---- reduce + softmax-weighted rsum ----
    if (t < 128) {
        float x = 0.f;
        #pragma unroll
        for (int g = 0; g < 16; ++g) x += red[g][t];
        float mx = -1e30f;
        #pragma unroll
        for (int r = 0; r < R_; ++r) mx = fmaxf(mx, x * rs_s[r]);
        float num = 0.f, den = 0.f;
        #pragma unroll
        for (int r = 0; r < R_; ++r) {
            const float e = __expf(x * rs_s[r] - mx);
            den += e;
            num = fmaf(rs_s[r], e, num);
        }
        w_s[t] = num / den;
    }
    __syncthreads();

    // ---- write Out[b, c, i-tile]: warp per c, 512B coalesced stores ----
    const int i4 = lane * 4;
    const float4 w4 = *(const float4*)&w_s[i4];
    float* op = Out + (long)b * C_ * M_ + i0 + i4;
    #pragma unroll 4
    for (int c = cg; c < C_; c += 16) {
        const float yv = y_s[c];
        float4 o = make_float4(w4.x * yv, w4.y * yv, w4.z * yv, w4.w * yv);
        *(float4*)&op[(long)c * M_] = o;
    }
}

// ---------------------------------------------------------------------------
extern "C" void kernel_launch(void* const* d_in, const int* in_sizes, int n_in,
                              void* d_out, int out_size)
{
    (void)in_sizes; (void)n_in; (void)out_size;
    const float* T     = (const float*)d_in[0];   // (B, C, M)
    const float* Wq    = (const float*)d_in[1];   // (C, D)
    const float* Wk    = (const float*)d_in[2];   // (C, D)
    const float* Wv    = (const float*)d_in[3];   // (C, DV)
    const float* Wout  = (const float*)d_in[4];   // (DV, C)
    const float* Rfull = (const float*)d_in[5];   // (R, M)
    float* Out = (float*)d_out;                   // (B, C, M)

    const float scale = 1.0f / sqrtf((float)D_);

    k_rowsum<<<(B_ * C_ + R_ + 7) / 8, 256>>>(T, Rfull);
    k_kv_partial<<<dim3(NCC, B_ / 4), 512>>>(Wk, Wv);
    k_kv_combine<<<B_, 512>>>();
    k_uy<<<C_ + 64, 256>>>(Wq, Wout, scale);
    k_scores_out<<<dim3(M_ / 128, B_), 512>>>(T, Out);
}